// round 2
// baseline (speedup 1.0000x reference)
#include <cuda_runtime.h>
#include <math.h>

#define D_MODEL 768
#define D_FF    3072
#define N_EXP   9
#define N_TOK   2048
#define MAXROWS 4096   // 2048 (expert-0 segment) + up to 2048 routed rows

// ---------------- scratch (device globals: no allocation allowed) ----------
__device__ float g_h[MAXROWS * D_FF];        // hidden activations (gelu output)
__device__ float g_y[MAXROWS * D_MODEL];     // FFN outputs per row
__device__ float g_p[N_TOK];                 // max softmax prob per token
__device__ int   g_e[N_TOK];                 // argmax expert per token
__device__ int   g_cnt[N_EXP];               // tokens routed to expert e (e>=1 used)
__device__ int   g_pos[N_EXP];               // assignment cursors
__device__ int   g_base[N_EXP];              // row base per expert segment
__device__ int   g_rowtok[MAXROWS];          // row -> token id
__device__ int   g_rowidx[N_TOK];            // token -> routed row (e != 0)

// ---------------- tiny bookkeeping kernels ---------------------------------
__global__ void zero_kernel() {
    int i = threadIdx.x;
    if (i < N_EXP) { g_cnt[i] = 0; g_pos[i] = 0; }
}

__global__ void router_kernel(const float* __restrict__ x,
                              const float* __restrict__ Ws,
                              const float* __restrict__ bs) {
    int warp = (blockIdx.x * blockDim.x + threadIdx.x) >> 5;
    int lane = threadIdx.x & 31;
    if (warp >= N_TOK) return;
    const float* xr = x + (size_t)warp * D_MODEL;

    float acc[N_EXP];
#pragma unroll
    for (int e = 0; e < N_EXP; e++) acc[e] = 0.0f;

    for (int d = lane; d < D_MODEL; d += 32) {
        float xv = xr[d];
        const float* wr = Ws + d * N_EXP;
#pragma unroll
        for (int e = 0; e < N_EXP; e++) acc[e] += xv * wr[e];
    }
#pragma unroll
    for (int e = 0; e < N_EXP; e++) {
#pragma unroll
        for (int o = 16; o; o >>= 1)
            acc[e] += __shfl_xor_sync(0xffffffffu, acc[e], o);
    }
    if (lane == 0) {
        float l[N_EXP];
        float lmax = -1e30f; int am = 0;
#pragma unroll
        for (int e = 0; e < N_EXP; e++) {
            l[e] = acc[e] + bs[e];
            if (l[e] > lmax) { lmax = l[e]; am = e; }   // first-max like jnp.argmax
        }
        float s = 0.0f;
#pragma unroll
        for (int e = 0; e < N_EXP; e++) s += expf(l[e] - lmax);
        g_p[warp] = 1.0f / s;   // max softmax prob
        g_e[warp] = am;
        atomicAdd(&g_cnt[am], 1);
    }
}

__global__ void scan_kernel() {
    int run = N_TOK;
    g_base[0] = 0;
    for (int e = 1; e < N_EXP; e++) { g_base[e] = run; run += g_cnt[e]; }
}

__global__ void assign_kernel() {
    int t = blockIdx.x * blockDim.x + threadIdx.x;
    if (t >= N_TOK) return;
    g_rowtok[t] = t;                 // expert-0 segment: identity
    int e = g_e[t];
    if (e != 0) {
        int s = atomicAdd(&g_pos[e], 1);
        int row = g_base[e] + s;
        g_rowtok[row] = t;
        g_rowidx[t]   = row;
    }
}

// ---------------- GEMM 1: h = gelu(x[tok] @ W1[e] + b1[e]) ------------------
// Tile 64x64x16, 128 threads, 8x4 micro-tile per thread.
__global__ void __launch_bounds__(128)
ffn1_kernel(const float* __restrict__ x,
            const float* __restrict__ W1,
            const float* __restrict__ b1) {
    const int e    = blockIdx.z;
    const int rows = (e == 0) ? N_TOK : g_cnt[e];
    const int m0   = blockIdx.y * 64;
    if (m0 >= rows) return;
    const int base = (e == 0) ? 0 : g_base[e];
    const int n0   = blockIdx.x * 64;

    __shared__ float As[16][68];   // 68*4B = 272B row stride (16B aligned)
    __shared__ float Bs[16][64];

    const int tid = threadIdx.x;
    const int am  = tid & 63;            // A: m within tile
    const int ak  = (tid >> 6) * 4;      // A: k quad start (0 or 4)
    const int bn  = (tid & 15) * 4;      // B: n quad
    const int bk  = tid >> 4;            // B: k row (0..7)
    const int ty  = tid >> 4;            // compute: row group (0..7)
    const int tx  = tid & 15;            // compute: col group (0..15)

    const float* arow = nullptr;
    {
        int gm = m0 + am;
        if (gm < rows) arow = x + (size_t)g_rowtok[base + gm] * D_MODEL;
    }
    const float* Bbase = W1 + (size_t)e * D_MODEL * D_FF + n0;

    float acc[8][4];
#pragma unroll
    for (int i = 0; i < 8; i++)
#pragma unroll
        for (int j = 0; j < 4; j++) acc[i][j] = 0.0f;

    for (int k0 = 0; k0 < D_MODEL; k0 += 16) {
#pragma unroll
        for (int i = 0; i < 2; i++) {
            int kk = ak + i * 8;
            float4 v = make_float4(0.f, 0.f, 0.f, 0.f);
            if (arow) v = *(const float4*)(arow + k0 + kk);
            As[kk + 0][am] = v.x; As[kk + 1][am] = v.y;
            As[kk + 2][am] = v.z; As[kk + 3][am] = v.w;
        }
#pragma unroll
        for (int i = 0; i < 2; i++) {
            int kk = bk + i * 8;
            *(float4*)&Bs[kk][bn] =
                *(const float4*)(Bbase + (size_t)(k0 + kk) * D_FF + bn);
        }
        __syncthreads();
#pragma unroll
        for (int k = 0; k < 16; k++) {
            float4 a0 = *(const float4*)&As[k][ty * 8];
            float4 a1 = *(const float4*)&As[k][ty * 8 + 4];
            float4 b  = *(const float4*)&Bs[k][tx * 4];
            float av[8] = {a0.x, a0.y, a0.z, a0.w, a1.x, a1.y, a1.z, a1.w};
            float bv[4] = {b.x, b.y, b.z, b.w};
#pragma unroll
            for (int i = 0; i < 8; i++)
#pragma unroll
                for (int j = 0; j < 4; j++) acc[i][j] += av[i] * bv[j];
        }
        __syncthreads();
    }

#pragma unroll
    for (int i = 0; i < 8; i++) {
        int m = m0 + ty * 8 + i;
        if (m >= rows) continue;
        float* hrow = g_h + (size_t)(base + m) * D_FF + n0 + tx * 4;
        const float* brow = b1 + (size_t)e * D_FF + n0 + tx * 4;
#pragma unroll
        for (int j = 0; j < 4; j++) {
            float v = acc[i][j] + brow[j];
            hrow[j] = 0.5f * v * (1.0f + erff(v * 0.70710678118654752f)); // exact gelu
        }
    }
}

// ---------------- GEMM 2: y = h @ W2[e] + b2[e] -----------------------------
__global__ void __launch_bounds__(128)
ffn2_kernel(const float* __restrict__ W2,
            const float* __restrict__ b2) {
    const int e    = blockIdx.z;
    const int rows = (e == 0) ? N_TOK : g_cnt[e];
    const int m0   = blockIdx.y * 64;
    if (m0 >= rows) return;
    const int base = (e == 0) ? 0 : g_base[e];
    const int n0   = blockIdx.x * 64;

    __shared__ float As[16][68];
    __shared__ float Bs[16][64];

    const int tid = threadIdx.x;
    const int am  = tid & 63;
    const int ak  = (tid >> 6) * 4;
    const int bn  = (tid & 15) * 4;
    const int bk  = tid >> 4;
    const int ty  = tid >> 4;
    const int tx  = tid & 15;

    const float* arow = nullptr;
    {
        int gm = m0 + am;
        if (gm < rows) arow = g_h + (size_t)(base + gm) * D_FF;
    }
    const float* Bbase = W2 + (size_t)e * D_FF * D_MODEL + n0;

    float acc[8][4];
#pragma unroll
    for (int i = 0; i < 8; i++)
#pragma unroll
        for (int j = 0; j < 4; j++) acc[i][j] = 0.0f;

    for (int k0 = 0; k0 < D_FF; k0 += 16) {
#pragma unroll
        for (int i = 0; i < 2; i++) {
            int kk = ak + i * 8;
            float4 v = make_float4(0.f, 0.f, 0.f, 0.f);
            if (arow) v = *(const float4*)(arow + k0 + kk);
            As[kk + 0][am] = v.x; As[kk + 1][am] = v.y;
            As[kk + 2][am] = v.z; As[kk + 3][am] = v.w;
        }
#pragma unroll
        for (int i = 0; i < 2; i++) {
            int kk = bk + i * 8;
            *(float4*)&Bs[kk][bn] =
                *(const float4*)(Bbase + (size_t)(k0 + kk) * D_MODEL + bn);
        }
        __syncthreads();
#pragma unroll
        for (int k = 0; k < 16; k++) {
            float4 a0 = *(const float4*)&As[k][ty * 8];
            float4 a1 = *(const float4*)&As[k][ty * 8 + 4];
            float4 b  = *(const float4*)&Bs[k][tx * 4];
            float av[8] = {a0.x, a0.y, a0.z, a0.w, a1.x, a1.y, a1.z, a1.w};
            float bv[4] = {b.x, b.y, b.z, b.w};
#pragma unroll
            for (int i = 0; i < 8; i++)
#pragma unroll
                for (int j = 0; j < 4; j++) acc[i][j] += av[i] * bv[j];
        }
        __syncthreads();
    }

#pragma unroll
    for (int i = 0; i < 8; i++) {
        int m = m0 + ty * 8 + i;
        if (m >= rows) continue;
        float* yrow = g_y + (size_t)(base + m) * D_MODEL + n0 + tx * 4;
        const float* brow = b2 + (size_t)e * D_MODEL + n0 + tx * 4;
#pragma unroll
        for (int j = 0; j < 4; j++) yrow[j] = acc[i][j] + brow[j];
    }
}

// ---------------- combine ---------------------------------------------------
__global__ void combine_kernel(float* __restrict__ out) {
    int idx = blockIdx.x * blockDim.x + threadIdx.x;
    if (idx >= N_TOK * D_MODEL) return;
    int t = idx / D_MODEL;
    float y0 = g_y[idx];                 // segment-0 row t at offset idx
    int e = g_e[t];
    float r;
    if (e == 0) {
        r = y0;                          // scaling = p/stopgrad(p) = 1
    } else {
        float p  = g_p[t];
        float ye = g_y[(size_t)g_rowidx[t] * D_MODEL + (idx - t * D_MODEL)];
        r = p * ye + (1.0f - p) * y0;
    }
    out[idx] = r;
}

// ---------------- launch ----------------------------------------------------
extern "C" void kernel_launch(void* const* d_in, const int* in_sizes, int n_in,
                              void* d_out, int out_size) {
    const float* x  = (const float*)d_in[0];
    const float* Ws = (const float*)d_in[1];
    const float* bs = (const float*)d_in[2];
    const float* W1 = (const float*)d_in[3];
    const float* b1 = (const float*)d_in[4];
    const float* W2 = (const float*)d_in[5];
    const float* b2 = (const float*)d_in[6];
    float* out = (float*)d_out;

    zero_kernel<<<1, 32>>>();
    router_kernel<<<N_TOK / 8, 256>>>(x, Ws, bs);
    scan_kernel<<<1, 1>>>();
    assign_kernel<<<N_TOK / 256, 256>>>();
    ffn1_kernel<<<dim3(D_FF / 64, N_TOK / 64, N_EXP), 128>>>(x, W1, b1);
    ffn2_kernel<<<dim3(D_MODEL / 64, N_TOK / 64, N_EXP), 128>>>(W2, b2);
    combine_kernel<<<(N_TOK * D_MODEL + 255) / 256, 256>>>(out);
}

// round 8
// speedup vs baseline: 2.9324x; 2.9324x over previous
#include <cuda_runtime.h>
#include <cstdint>
#include <math.h>

#define D_MODEL 768
#define D_FF    3072
#define N_EXP   9
#define N_TOK   2048
#define MAXROWS 4096

// ---------------- scratch (device globals: no allocation allowed) ----------
__device__ float g_h[MAXROWS * D_FF];          // hidden activations (gelu out)
__device__ float g_y[MAXROWS * D_MODEL];       // FFN outputs per row
__device__ float g_p[N_TOK];
__device__ int   g_e[N_TOK];
__device__ int   g_cnt[N_EXP];
__device__ int   g_pos[N_EXP];
__device__ int   g_base[N_EXP];
__device__ int   g_rowtok[MAXROWS];
__device__ int   g_rowidx[N_TOK];

// ---------------- cp.async helpers (sm_80+, compute_103-safe) ---------------
__device__ __forceinline__ uint32_t smem_u32(const void* p) {
    uint32_t a;
    asm("{ .reg .u64 t; cvta.to.shared.u64 t, %1; cvt.u32.u64 %0, t; }"
        : "=r"(a) : "l"(p));
    return a;
}
#define CP_ASYNC16(dst_u32, src_ptr) \
    asm volatile("cp.async.cg.shared.global [%0], [%1], 16;" \
        :: "r"(dst_u32), "l"(src_ptr))
#define CP_COMMIT() asm volatile("cp.async.commit_group;")
#define CP_WAIT1()  asm volatile("cp.async.wait_group 1;")
#define CP_WAIT0()  asm volatile("cp.async.wait_group 0;")

__device__ __forceinline__ uint32_t to_tf32(float v) {
    uint32_t r;
    asm("cvt.rna.tf32.f32 %0, %1;" : "=r"(r) : "f"(v));
    return r;
}

__device__ __forceinline__ void mma_tf32(float* c, const uint32_t* a,
                                         const uint32_t* b) {
    asm volatile(
        "mma.sync.aligned.m16n8k8.row.col.f32.tf32.tf32.f32 "
        "{%0,%1,%2,%3}, {%4,%5,%6,%7}, {%8,%9}, {%0,%1,%2,%3};"
        : "+f"(c[0]), "+f"(c[1]), "+f"(c[2]), "+f"(c[3])
        : "r"(a[0]), "r"(a[1]), "r"(a[2]), "r"(a[3]),
          "r"(b[0]), "r"(b[1]));
}

// ---------------- tiny bookkeeping kernels ---------------------------------
__global__ void zero_kernel() {
    int i = threadIdx.x;
    if (i < N_EXP) { g_cnt[i] = 0; g_pos[i] = 0; }
}

__global__ void router_kernel(const float* __restrict__ x,
                              const float* __restrict__ Ws,
                              const float* __restrict__ bs) {
    int warp = (blockIdx.x * blockDim.x + threadIdx.x) >> 5;
    int lane = threadIdx.x & 31;
    if (warp >= N_TOK) return;
    const float* xr = x + (size_t)warp * D_MODEL;
    float acc[N_EXP];
#pragma unroll
    for (int e = 0; e < N_EXP; e++) acc[e] = 0.0f;
    for (int d = lane; d < D_MODEL; d += 32) {
        float xv = xr[d];
        const float* wr = Ws + d * N_EXP;
#pragma unroll
        for (int e = 0; e < N_EXP; e++) acc[e] += xv * wr[e];
    }
#pragma unroll
    for (int e = 0; e < N_EXP; e++) {
#pragma unroll
        for (int o = 16; o; o >>= 1)
            acc[e] += __shfl_xor_sync(0xffffffffu, acc[e], o);
    }
    if (lane == 0) {
        float l[N_EXP];
        float lmax = -1e30f; int am = 0;
#pragma unroll
        for (int e = 0; e < N_EXP; e++) {
            l[e] = acc[e] + bs[e];
            if (l[e] > lmax) { lmax = l[e]; am = e; }
        }
        float s = 0.0f;
#pragma unroll
        for (int e = 0; e < N_EXP; e++) s += expf(l[e] - lmax);
        g_p[warp] = 1.0f / s;
        g_e[warp] = am;
        atomicAdd(&g_cnt[am], 1);
    }
}

__global__ void scan_kernel() {
    int run = N_TOK;
    g_base[0] = 0;
    for (int e = 1; e < N_EXP; e++) { g_base[e] = run; run += g_cnt[e]; }
}

__global__ void assign_kernel() {
    int t = blockIdx.x * blockDim.x + threadIdx.x;
    if (t >= N_TOK) return;
    g_rowtok[t] = t;
    int e = g_e[t];
    if (e != 0) {
        int s = atomicAdd(&g_pos[e], 1);
        int row = g_base[e] + s;
        g_rowtok[row] = t;
        g_rowidx[t]   = row;
    }
}

// ---------------- mma.sync tf32 GEMM ----------------------------------------
// CTA tile 128(m) x 128(n) x 16(k). 256 threads = 8 warps, 4(m) x 2(n),
// warp tile 32x64. A smem [m][k] pitch 20 floats; B smem [k][n] pitch 136.
// Double-buffered cp.async pipeline. Total smem = 37,888 B (< 48 KB: no opt-in).
#define KCHUNK 16
#define APITCH 20
#define BPITCH 136
#define AFLOATS (128 * APITCH)        // 2560
#define BFLOATS (KCHUNK * BPITCH)     // 2176
#define SM_A0 0
#define SM_A1 AFLOATS
#define SM_B0 (2 * AFLOATS)
#define SM_B1 (2 * AFLOATS + BFLOATS)
#define SMEM_FLOATS (2 * AFLOATS + 2 * BFLOATS)   // 9472 floats = 37888 B

template<int KDIM, int NTOT, bool GATHER, bool DO_GELU>
__global__ void __launch_bounds__(256, 2)
gemm_mma(const float* __restrict__ A, const float* __restrict__ Bw,
         const float* __restrict__ bias, float* __restrict__ outp) {
    const int e    = blockIdx.z;
    const int rows = (e == 0) ? N_TOK : g_cnt[e];
    const int m0   = blockIdx.y * 128;
    if (m0 >= rows) return;
    const int base = (e == 0) ? 0 : g_base[e];
    const int n0   = blockIdx.x * 128;

    __shared__ float sm[SMEM_FLOATS];
    const uint32_t smb = smem_u32(sm);

    const int tid  = threadIdx.x;
    const int wid  = tid >> 5;
    const int lane = tid & 31;
    const int wm   = wid & 3;      // m-warp 0..3
    const int wn   = wid >> 2;     // n-warp 0..1
    const int qm   = lane >> 2;    // 0..7
    const int qk   = lane & 3;     // 0..3

    // ---- global source pointers (constant across chunks; add k offset) ----
    // A: 128 rows x 16 floats per chunk = 512 float4; thread covers 2.
    const int arow_lo = tid >> 2;      // 0..63
    const int af4     = tid & 3;       // 0..3  (float4 within 16-float k chunk)
    const float* asrc[2];
    uint32_t adst[2];
#pragma unroll
    for (int i = 0; i < 2; i++) {
        int r  = arow_lo + i * 64;          // 0..127 tile m row
        int m  = m0 + r;
        int mm = (m < rows) ? m : (rows - 1);
        const float* rowp;
        if (GATHER) rowp = A + (size_t)g_rowtok[base + mm] * KDIM;
        else        rowp = A + (size_t)(base + mm) * KDIM;
        asrc[i] = rowp + af4 * 4;
        adst[i] = (uint32_t)((r * APITCH + af4 * 4) * 4);
    }
    // B: 16 k-rows x 128 floats per chunk = 512 float4; thread covers 2.
    const int bk_lo = tid >> 5;        // 0..7
    const int bf4   = tid & 31;        // 0..31 (float4 within 128-float n row)
    const float* Bbase = Bw + (size_t)e * KDIM * NTOT + n0 + bf4 * 4;
    uint32_t bdst[2];
#pragma unroll
    for (int i = 0; i < 2; i++) {
        int kk = bk_lo + i * 8;             // 0..15 tile k row
        bdst[i] = (uint32_t)((kk * BPITCH + bf4 * 4) * 4);
    }

    const uint32_t abuf[2] = { smb + SM_A0 * 4, smb + SM_A1 * 4 };
    const uint32_t bbuf[2] = { smb + SM_B0 * 4, smb + SM_B1 * 4 };
    const int aoff[2] = { SM_A0, SM_A1 };
    const int boff[2] = { SM_B0, SM_B1 };

    auto load_chunk = [&](int buf, int k0) {
#pragma unroll
        for (int i = 0; i < 2; i++)
            CP_ASYNC16(abuf[buf] + adst[i], asrc[i] + k0);
#pragma unroll
        for (int i = 0; i < 2; i++)
            CP_ASYNC16(bbuf[buf] + bdst[i],
                       Bbase + (size_t)(k0 + bk_lo + i * 8) * NTOT);
        CP_COMMIT();
    };

    float acc[2][8][4];
#pragma unroll
    for (int tm = 0; tm < 2; tm++)
#pragma unroll
        for (int tn = 0; tn < 8; tn++)
#pragma unroll
            for (int j = 0; j < 4; j++) acc[tm][tn][j] = 0.0f;

    const int NC = KDIM / KCHUNK;
    load_chunk(0, 0);

    for (int ch = 0; ch < NC; ch++) {
        int buf = ch & 1;
        if (ch + 1 < NC) { load_chunk((ch + 1) & 1, (ch + 1) * KCHUNK); CP_WAIT1(); }
        else             { CP_WAIT0(); }
        __syncthreads();

        const float* As = sm + aoff[buf];
        const float* Bs = sm + boff[buf];
#pragma unroll
        for (int k8 = 0; k8 < KCHUNK / 8; k8++) {
            const int kk0 = k8 * 8;
            uint32_t afr[2][4];
#pragma unroll
            for (int tm = 0; tm < 2; tm++) {
                const float* ap = As + (wm * 32 + tm * 16 + qm) * APITCH + kk0 + qk;
                afr[tm][0] = to_tf32(ap[0]);
                afr[tm][1] = to_tf32(ap[8 * APITCH]);
                afr[tm][2] = to_tf32(ap[4]);
                afr[tm][3] = to_tf32(ap[8 * APITCH + 4]);
            }
            uint32_t bfr[8][2];
#pragma unroll
            for (int tn = 0; tn < 8; tn++) {
                const float* bp = Bs + (kk0 + qk) * BPITCH + wn * 64 + tn * 8 + qm;
                bfr[tn][0] = to_tf32(bp[0]);
                bfr[tn][1] = to_tf32(bp[4 * BPITCH]);
            }
#pragma unroll
            for (int tm = 0; tm < 2; tm++)
#pragma unroll
                for (int tn = 0; tn < 8; tn++)
                    mma_tf32(acc[tm][tn], afr[tm], bfr[tn]);
        }
        __syncthreads();
    }

    // ---- epilogue: bias (+ gelu), direct global stores ----
    const float* bp_e = bias + (size_t)e * NTOT + n0 + wn * 64;
#pragma unroll
    for (int tm = 0; tm < 2; tm++) {
        int r0 = m0 + wm * 32 + tm * 16 + qm;
#pragma unroll
        for (int half = 0; half < 2; half++) {
            int r = r0 + half * 8;
            if (r >= rows) continue;
            float* orow = outp + (size_t)(base + r) * NTOT + n0 + wn * 64;
#pragma unroll
            for (int tn = 0; tn < 8; tn++) {
                int c = tn * 8 + qk * 2;
                float v0 = acc[tm][tn][half * 2 + 0] + __ldg(bp_e + c + 0);
                float v1 = acc[tm][tn][half * 2 + 1] + __ldg(bp_e + c + 1);
                if (DO_GELU) {
                    v0 = 0.5f * v0 * (1.0f + erff(v0 * 0.70710678118654752f));
                    v1 = 0.5f * v1 * (1.0f + erff(v1 * 0.70710678118654752f));
                }
                float2 o = make_float2(v0, v1);
                *(float2*)(orow + c) = o;
            }
        }
    }
}

// ---------------- combine ---------------------------------------------------
__global__ void combine_kernel(float* __restrict__ out) {
    int idx = blockIdx.x * blockDim.x + threadIdx.x;
    if (idx >= N_TOK * D_MODEL) return;
    int t = idx / D_MODEL;
    float y0 = g_y[idx];
    int e = g_e[t];
    float r;
    if (e == 0) {
        r = y0;
    } else {
        float p  = g_p[t];
        float ye = g_y[(size_t)g_rowidx[t] * D_MODEL + (idx - t * D_MODEL)];
        r = p * ye + (1.0f - p) * y0;
    }
    out[idx] = r;
}

// ---------------- launch ----------------------------------------------------
extern "C" void kernel_launch(void* const* d_in, const int* in_sizes, int n_in,
                              void* d_out, int out_size) {
    const float* x  = (const float*)d_in[0];
    const float* Ws = (const float*)d_in[1];
    const float* bs = (const float*)d_in[2];
    const float* W1 = (const float*)d_in[3];
    const float* b1 = (const float*)d_in[4];
    const float* W2 = (const float*)d_in[5];
    const float* b2 = (const float*)d_in[6];
    float* out = (float*)d_out;

    // CRITICAL: __device__ symbols must be resolved to DEVICE addresses here.
    // Passing the symbol name directly from host code passes the host shadow
    // address (which GB300's ATS happily dereferences -> silent wrong results).
    float* hbuf; cudaGetSymbolAddress((void**)&hbuf, g_h);
    float* ybuf; cudaGetSymbolAddress((void**)&ybuf, g_y);

    zero_kernel<<<1, 32>>>();
    router_kernel<<<N_TOK / 8, 256>>>(x, Ws, bs);
    scan_kernel<<<1, 1>>>();
    assign_kernel<<<N_TOK / 256, 256>>>();

    // GEMM1: h = gelu(x @ W1 + b1); A gathered token rows, B = W1 [d][f]
    gemm_mma<D_MODEL, D_FF, true, true>
        <<<dim3(D_FF / 128, N_TOK / 128, N_EXP), 256>>>(
            x, W1, b1, hbuf);
    // GEMM2: y = h @ W2 + b2; B = W2 [f][d]
    gemm_mma<D_FF, D_MODEL, false, false>
        <<<dim3(D_MODEL / 128, N_TOK / 128, N_EXP), 256>>>(
            hbuf, W2, b2, ybuf);

    combine_kernel<<<(N_TOK * D_MODEL + 255) / 256, 256>>>(out);
}

// round 11
// speedup vs baseline: 2.9675x; 1.0120x over previous
#include <cuda_runtime.h>
#include <cstdint>
#include <math.h>

#define D_MODEL 768
#define D_FF    3072
#define N_EXP   9
#define N_TOK   2048
#define MAXROWS 4096

// ---------------- scratch (device globals: no allocation allowed) ----------
__device__ float g_h[MAXROWS * D_FF];          // hidden activations (gelu out)
__device__ float g_y[MAXROWS * D_MODEL];       // FFN outputs per row
__device__ float g_p[N_TOK];
__device__ int   g_e[N_TOK];
__device__ int   g_cnt[N_EXP];
__device__ int   g_pos[N_EXP];
__device__ int   g_base[N_EXP];
__device__ int   g_rowtok[MAXROWS];
__device__ int   g_rowidx[N_TOK];

// ---------------- cp.async helpers (sm_80+, compute_103-safe) ---------------
__device__ __forceinline__ uint32_t smem_u32(const void* p) {
    uint32_t a;
    asm("{ .reg .u64 t; cvta.to.shared.u64 t, %1; cvt.u32.u64 %0, t; }"
        : "=r"(a) : "l"(p));
    return a;
}
#define CP_ASYNC16(dst_u32, src_ptr) \
    asm volatile("cp.async.cg.shared.global [%0], [%1], 16;" \
        :: "r"(dst_u32), "l"(src_ptr))
#define CP_COMMIT() asm volatile("cp.async.commit_group;")
#define CP_WAIT1()  asm volatile("cp.async.wait_group 1;")
#define CP_WAIT0()  asm volatile("cp.async.wait_group 0;")

__device__ __forceinline__ uint32_t to_tf32(float v) {
    uint32_t r;
    asm("cvt.rna.tf32.f32 %0, %1;" : "=r"(r) : "f"(v));
    return r;
}

__device__ __forceinline__ void mma_tf32(float* c, const uint32_t* a,
                                         const uint32_t* b) {
    asm volatile(
        "mma.sync.aligned.m16n8k8.row.col.f32.tf32.tf32.f32 "
        "{%0,%1,%2,%3}, {%4,%5,%6,%7}, {%8,%9}, {%0,%1,%2,%3};"
        : "+f"(c[0]), "+f"(c[1]), "+f"(c[2]), "+f"(c[3])
        : "r"(a[0]), "r"(a[1]), "r"(a[2]), "r"(a[3]),
          "r"(b[0]), "r"(b[1]));
}

// ---------------- tiny bookkeeping kernels ---------------------------------
__global__ void zero_kernel() {
    int i = threadIdx.x;
    if (i < N_EXP) { g_cnt[i] = 0; g_pos[i] = 0; }
}

__global__ void router_kernel(const float* __restrict__ x,
                              const float* __restrict__ Ws,
                              const float* __restrict__ bs) {
    int warp = (blockIdx.x * blockDim.x + threadIdx.x) >> 5;
    int lane = threadIdx.x & 31;
    if (warp >= N_TOK) return;
    const float* xr = x + (size_t)warp * D_MODEL;
    float acc[N_EXP];
#pragma unroll
    for (int e = 0; e < N_EXP; e++) acc[e] = 0.0f;
    for (int d = lane; d < D_MODEL; d += 32) {
        float xv = xr[d];
        const float* wr = Ws + d * N_EXP;
#pragma unroll
        for (int e = 0; e < N_EXP; e++) acc[e] += xv * wr[e];
    }
#pragma unroll
    for (int e = 0; e < N_EXP; e++) {
#pragma unroll
        for (int o = 16; o; o >>= 1)
            acc[e] += __shfl_xor_sync(0xffffffffu, acc[e], o);
    }
    if (lane == 0) {
        float l[N_EXP];
        float lmax = -1e30f; int am = 0;
#pragma unroll
        for (int e = 0; e < N_EXP; e++) {
            l[e] = acc[e] + bs[e];
            if (l[e] > lmax) { lmax = l[e]; am = e; }
        }
        float s = 0.0f;
#pragma unroll
        for (int e = 0; e < N_EXP; e++) s += expf(l[e] - lmax);
        g_p[warp] = 1.0f / s;
        g_e[warp] = am;
        atomicAdd(&g_cnt[am], 1);
    }
}

__global__ void scan_kernel() {
    int run = N_TOK;
    g_base[0] = 0;
    for (int e = 1; e < N_EXP; e++) { g_base[e] = run; run += g_cnt[e]; }
}

__global__ void assign_kernel() {
    int t = blockIdx.x * blockDim.x + threadIdx.x;
    if (t >= N_TOK) return;
    g_rowtok[t] = t;
    int e = g_e[t];
    if (e != 0) {
        int s = atomicAdd(&g_pos[e], 1);
        int row = g_base[e] + s;
        g_rowtok[row] = t;
        g_rowidx[t]   = row;
    }
}

// ---------------- mma.sync tf32 GEMM ----------------------------------------
// CTA tile 128(m) x 128(n) x 32(k). 256 threads = 8 warps, 4(m) x 2(n),
// warp tile 32x64. A smem [m][k] pitch 36 floats; B smem [k][n] pitch 136.
// Double-buffered cp.async pipeline. Dynamic smem 71,680 B (opt-in).
#define KCHUNK 32
#define APITCH 36
#define BPITCH 136
#define AFLOATS (128 * APITCH)        // 4608
#define BFLOATS (KCHUNK * BPITCH)     // 4352
#define SM_A0 0
#define SM_A1 AFLOATS
#define SM_B0 (2 * AFLOATS)
#define SM_B1 (2 * AFLOATS + BFLOATS)
#define SMEM_FLOATS (2 * AFLOATS + 2 * BFLOATS)   // 17920 floats = 71680 B

template<int KDIM, int NTOT, bool GATHER, bool DO_GELU>
__global__ void __launch_bounds__(256, 2)
gemm_mma(const float* __restrict__ A, const float* __restrict__ Bw,
         const float* __restrict__ bias, float* __restrict__ outp) {
    const int e    = blockIdx.z;
    const int rows = (e == 0) ? N_TOK : g_cnt[e];
    const int m0   = blockIdx.y * 128;
    if (m0 >= rows) return;
    const int base = (e == 0) ? 0 : g_base[e];
    const int n0   = blockIdx.x * 128;

    extern __shared__ float sm[];
    const uint32_t smb = smem_u32(sm);

    const int tid  = threadIdx.x;
    const int wid  = tid >> 5;
    const int lane = tid & 31;
    const int wm   = wid & 3;      // m-warp 0..3
    const int wn   = wid >> 2;     // n-warp 0..1
    const int qm   = lane >> 2;    // 0..7
    const int qk   = lane & 3;     // 0..3

    // ---- global source pointers (constant across chunks; add k offset) ----
    // A: 128 rows x 32 floats per chunk = 1024 float4; thread covers 4.
    const int arow_lo = tid >> 3;      // 0..31
    const int af4     = tid & 7;       // 0..7  (float4 within 32-float k chunk)
    const float* asrc[4];
    uint32_t adst[4];
#pragma unroll
    for (int i = 0; i < 4; i++) {
        int r  = arow_lo + i * 32;          // 0..127 tile m row
        int m  = m0 + r;
        int mm = (m < rows) ? m : (rows - 1);
        const float* rowp;
        if (GATHER) rowp = A + (size_t)g_rowtok[base + mm] * KDIM;
        else        rowp = A + (size_t)(base + mm) * KDIM;
        asrc[i] = rowp + af4 * 4;
        adst[i] = (uint32_t)((r * APITCH + af4 * 4) * 4);
    }
    // B: 32 k-rows x 128 floats per chunk = 1024 float4; thread covers 4.
    const int bk_lo = tid >> 5;        // 0..7
    const int bf4   = tid & 31;        // 0..31 (float4 within 128-float n row)
    const float* Bbase = Bw + (size_t)e * KDIM * NTOT + n0 + bf4 * 4;
    uint32_t bdst[4];
#pragma unroll
    for (int i = 0; i < 4; i++) {
        int kk = bk_lo + i * 8;             // 0..31 tile k row
        bdst[i] = (uint32_t)((kk * BPITCH + bf4 * 4) * 4);
    }

    const uint32_t abuf[2] = { smb + SM_A0 * 4, smb + SM_A1 * 4 };
    const uint32_t bbuf[2] = { smb + SM_B0 * 4, smb + SM_B1 * 4 };
    const int aoff[2] = { SM_A0, SM_A1 };
    const int boff[2] = { SM_B0, SM_B1 };

    auto load_chunk = [&](int buf, int k0) {
#pragma unroll
        for (int i = 0; i < 4; i++)
            CP_ASYNC16(abuf[buf] + adst[i], asrc[i] + k0);
#pragma unroll
        for (int i = 0; i < 4; i++)
            CP_ASYNC16(bbuf[buf] + bdst[i],
                       Bbase + (size_t)(k0 + bk_lo + i * 8) * NTOT);
        CP_COMMIT();
    };

    float acc[2][8][4];
#pragma unroll
    for (int tm = 0; tm < 2; tm++)
#pragma unroll
        for (int tn = 0; tn < 8; tn++)
#pragma unroll
            for (int j = 0; j < 4; j++) acc[tm][tn][j] = 0.0f;

    const int NC = KDIM / KCHUNK;
    load_chunk(0, 0);

    for (int ch = 0; ch < NC; ch++) {
        int buf = ch & 1;
        if (ch + 1 < NC) { load_chunk((ch + 1) & 1, (ch + 1) * KCHUNK); CP_WAIT1(); }
        else             { CP_WAIT0(); }
        __syncthreads();

        const float* As = sm + aoff[buf];
        const float* Bs = sm + boff[buf];
#pragma unroll
        for (int k8 = 0; k8 < KCHUNK / 8; k8++) {
            const int kk0 = k8 * 8;
            uint32_t afr[2][4];
#pragma unroll
            for (int tm = 0; tm < 2; tm++) {
                const float* ap = As + (wm * 32 + tm * 16 + qm) * APITCH + kk0 + qk;
                afr[tm][0] = to_tf32(ap[0]);
                afr[tm][1] = to_tf32(ap[8 * APITCH]);
                afr[tm][2] = to_tf32(ap[4]);
                afr[tm][3] = to_tf32(ap[8 * APITCH + 4]);
            }
            uint32_t bfr[8][2];
#pragma unroll
            for (int tn = 0; tn < 8; tn++) {
                const float* bp = Bs + (kk0 + qk) * BPITCH + wn * 64 + tn * 8 + qm;
                bfr[tn][0] = to_tf32(bp[0]);
                bfr[tn][1] = to_tf32(bp[4 * BPITCH]);
            }
#pragma unroll
            for (int tm = 0; tm < 2; tm++)
#pragma unroll
                for (int tn = 0; tn < 8; tn++)
                    mma_tf32(acc[tm][tn], afr[tm], bfr[tn]);
        }
        __syncthreads();
    }

    // ---- epilogue: bias (+ gelu), direct global stores ----
    const float* bp_e = bias + (size_t)e * NTOT + n0 + wn * 64;
#pragma unroll
    for (int tm = 0; tm < 2; tm++) {
        int r0 = m0 + wm * 32 + tm * 16 + qm;
#pragma unroll
        for (int half = 0; half < 2; half++) {
            int r = r0 + half * 8;
            if (r >= rows) continue;
            float* orow = outp + (size_t)(base + r) * NTOT + n0 + wn * 64;
#pragma unroll
            for (int tn = 0; tn < 8; tn++) {
                int c = tn * 8 + qk * 2;
                float v0 = acc[tm][tn][half * 2 + 0] + __ldg(bp_e + c + 0);
                float v1 = acc[tm][tn][half * 2 + 1] + __ldg(bp_e + c + 1);
                if (DO_GELU) {
                    v0 = 0.5f * v0 * (1.0f + erff(v0 * 0.70710678118654752f));
                    v1 = 0.5f * v1 * (1.0f + erff(v1 * 0.70710678118654752f));
                }
                float2 o = make_float2(v0, v1);
                *(float2*)(orow + c) = o;
            }
        }
    }
}

// ---------------- combine ---------------------------------------------------
__global__ void combine_kernel(float* __restrict__ out) {
    int idx = blockIdx.x * blockDim.x + threadIdx.x;
    if (idx >= N_TOK * D_MODEL) return;
    int t = idx / D_MODEL;
    float y0 = g_y[idx];
    int e = g_e[t];
    float r;
    if (e == 0) {
        r = y0;
    } else {
        float p  = g_p[t];
        float ye = g_y[(size_t)g_rowidx[t] * D_MODEL + (idx - t * D_MODEL)];
        r = p * ye + (1.0f - p) * y0;
    }
    out[idx] = r;
}

// ---------------- launch ----------------------------------------------------
extern "C" void kernel_launch(void* const* d_in, const int* in_sizes, int n_in,
                              void* d_out, int out_size) {
    const float* x  = (const float*)d_in[0];
    const float* Ws = (const float*)d_in[1];
    const float* bs = (const float*)d_in[2];
    const float* W1 = (const float*)d_in[3];
    const float* b1 = (const float*)d_in[4];
    const float* W2 = (const float*)d_in[5];
    const float* b2 = (const float*)d_in[6];
    float* out = (float*)d_out;

    // CRITICAL: __device__ symbols must be resolved to DEVICE addresses here.
    float* hbuf; cudaGetSymbolAddress((void**)&hbuf, g_h);
    float* ybuf; cudaGetSymbolAddress((void**)&ybuf, g_y);

    const int smem_bytes = SMEM_FLOATS * 4;   // 71680
    cudaFuncSetAttribute((const void*)gemm_mma<D_MODEL, D_FF, true, true>,
                         cudaFuncAttributeMaxDynamicSharedMemorySize, smem_bytes);
    cudaFuncSetAttribute((const void*)gemm_mma<D_FF, D_MODEL, false, false>,
                         cudaFuncAttributeMaxDynamicSharedMemorySize, smem_bytes);

    zero_kernel<<<1, 32>>>();
    router_kernel<<<N_TOK / 8, 256>>>(x, Ws, bs);
    scan_kernel<<<1, 1>>>();
    assign_kernel<<<N_TOK / 256, 256>>>();

    // GEMM1: h = gelu(x @ W1 + b1); A gathered token rows, B = W1 [d][f]
    gemm_mma<D_MODEL, D_FF, true, true>
        <<<dim3(D_FF / 128, N_TOK / 128, N_EXP), 256, smem_bytes>>>(
            x, W1, b1, hbuf);
    // GEMM2: y = h @ W2 + b2; B = W2 [f][d]
    gemm_mma<D_FF, D_MODEL, false, false>
        <<<dim3(D_MODEL / 128, N_TOK / 128, N_EXP), 256, smem_bytes>>>(
            hbuf, W2, b2, ybuf);

    combine_kernel<<<(N_TOK * D_MODEL + 255) / 256, 256>>>(out);
}